// round 4
// baseline (speedup 1.0000x reference)
#include <cuda_runtime.h>

// MultiScaleRoIAlign: 4-level FPN, RoIAlign(aligned=False), OUT=7, SR=2.
// feats: [2,256,200,200],[2,256,100,100],[2,256,50,50],[2,256,25,25] fp32
// boxes: [2,256,4] fp32 -> out: [512,256,7,7] fp32
//
// One block per RoI. RoI's sampled region staged to smem 8 channels at a
// time (warp->row, lane->col; division-free, coalesced). Pooling uses the
// exact separable form of the 2x2-sample bilinear mean: per bin,
//   acc = sum_i cy[i] * sum_j cx[j] * S[R[i] + X[j]]
// with all per-bin geometry hoisted into registers (constant across the
// 32 channel-group iterations). Warp w computes channel c0+w.

#define NLVL 4
#define GRP 8
#define MAXCELLS 1024

__global__ __launch_bounds__(256, 3) void roi_align_kernel(
    const float* __restrict__ f0, const float* __restrict__ f1,
    const float* __restrict__ f2, const float* __restrict__ f3,
    const float* __restrict__ boxes, float* __restrict__ out)
{
    const int r    = blockIdx.x;     // roi 0..511
    const int tid  = threadIdx.x;    // 0..255
    const int w    = tid >> 5;
    const int lane = tid & 31;
    const int b    = r >> 8;

    // ---- per-RoI geometry (redundant per thread) ----
    const float bx1 = boxes[r * 4 + 0];
    const float by1 = boxes[r * 4 + 1];
    const float bx2 = boxes[r * 4 + 2];
    const float by2 = boxes[r * 4 + 3];

    const float area = (bx2 - bx1) * (by2 - by1);
    float lv = floorf(4.0f + log2f(sqrtf(area) / 224.0f + 1e-6f));
    lv = fminf(fmaxf(lv, 2.0f), 5.0f);
    const int level = (int)lv - 2;

    const int   Htab[NLVL]  = {200, 100, 50, 25};
    const float sctab[NLVL] = {0.25f, 0.125f, 0.0625f, 0.03125f};
    const int   H  = Htab[level];
    const int   W  = H;
    const float sc = sctab[level];
    const float* feat = (level == 0) ? f0 : (level == 1) ? f1 : (level == 2) ? f2 : f3;

    const float x1 = bx1 * sc, y1 = by1 * sc;
    const float roi_w = fmaxf(bx2 * sc - x1, 1.0f);
    const float roi_h = fmaxf(by2 * sc - y1, 1.0f);
    const float bin_w = roi_w / 7.0f;
    const float bin_h = roi_h / 7.0f;

    // ---- sample tables ----
    __shared__ int   s_yl[14], s_yh[14], s_xl[14], s_xh[14];
    __shared__ float s_ly[14], s_lx[14], s_vy[14], s_vx[14];
    __shared__ float s_reg[GRP * MAXCELLS];   // 32 KB

    if (tid < 30) {
        const bool isx = (tid >= 16);            // 0..13 -> y, 16..29 -> x
        const int  jj  = isx ? (tid - 16) : tid;
        if (jj < 14) {
            const int ph = jj >> 1;
            const int ii = jj & 1;
            const float g = (float)ph + ((float)ii + 0.5f) * 0.5f;  // ph + (i+0.5)/SR
            float pos = isx ? (x1 + g * bin_w) : (y1 + g * bin_h);
            const float lim = (float)H;                             // square
            const float vld = (pos >= -1.0f && pos <= lim) ? 1.0f : 0.0f;
            pos = fmaxf(pos, 0.0f);
            int lo = (int)pos;
            int hi;
            if (lo >= H - 1) { lo = H - 1; hi = H - 1; pos = (float)lo; }
            else             { hi = lo + 1; }
            const float frac = pos - (float)lo;
            if (isx) { s_xl[jj] = lo; s_xh[jj] = hi; s_lx[jj] = frac; s_vx[jj] = vld; }
            else     { s_yl[jj] = lo; s_yh[jj] = hi; s_ly[jj] = frac; s_vy[jj] = vld; }
        }
    }
    __syncthreads();

    // sample positions are monotone -> region bounds from table ends
    const int ry0 = s_yl[0], ry1 = s_yh[13];
    const int rx0 = s_xl[0], rx1 = s_xh[13];
    const int nrows = ry1 - ry0 + 1;
    const int ncols = rx1 - rx0 + 1;
    const int cells = nrows * ncols;

    const size_t plane = (size_t)H * W;

    if (cells <= MAXCELLS) {
        // ---- per-lane bin geometry, hoisted out of the channel loop ----
        // lane handles bin (lane) and bin (lane+32) if < 49
        int   Roff[2][4], Xoff[2][4];
        float Cy[2][4],   Cx[2][4];
        #pragma unroll
        for (int chk = 0; chk < 2; chk++) {
            const int bin = lane + 32 * chk;
            if (bin < 49) {
                const int ph = bin / 7;          // const-div -> mul/shift
                const int pw = bin - ph * 7;
                #pragma unroll
                for (int s = 0; s < 2; s++) {
                    const int jy = 2 * ph + s;
                    const int jx = 2 * pw + s;
                    const float vy = s_vy[jy] * 0.25f;   // fold mean /4 into cy
                    Roff[chk][2 * s + 0] = (s_yl[jy] - ry0) * ncols;
                    Roff[chk][2 * s + 1] = (s_yh[jy] - ry0) * ncols;
                    Cy[chk][2 * s + 0] = vy * (1.0f - s_ly[jy]);
                    Cy[chk][2 * s + 1] = vy * s_ly[jy];
                    Xoff[chk][2 * s + 0] = s_xl[jx] - rx0;
                    Xoff[chk][2 * s + 1] = s_xh[jx] - rx0;
                    Cx[chk][2 * s + 0] = s_vx[jx] * (1.0f - s_lx[jx]);
                    Cx[chk][2 * s + 1] = s_vx[jx] * s_lx[jx];
                }
            }
        }

        const float* fbase = feat + (size_t)b * 256 * plane + (size_t)ry0 * W + rx0;

        for (int c0 = 0; c0 < 256; c0 += GRP) {
            // ---- stage GRP channel-regions: warp->row, lane->col ----
            const float* fp = fbase + (size_t)c0 * plane;
            float* dst = s_reg;
            for (int g = 0; g < GRP; g++) {
                for (int row = w; row < nrows; row += 8) {
                    const float* src = fp + (size_t)row * W;
                    const int rb = row * ncols;
                    for (int col = lane; col < ncols; col += 32)
                        dst[rb + col] = src[col];
                }
                fp  += plane;
                dst += MAXCELLS;
            }
            __syncthreads();

            // ---- compute: warp w -> channel c0+w ----
            const float* S = s_reg + w * MAXCELLS;
            float* op = out + ((size_t)r * 256 + (c0 + w)) * 49;
            #pragma unroll
            for (int chk = 0; chk < 2; chk++) {
                const int bin = lane + 32 * chk;
                if (bin < 49) {
                    float acc = 0.0f;
                    #pragma unroll
                    for (int i = 0; i < 4; i++) {
                        const float* Sr = S + Roff[chk][i];
                        const float rs = Cx[chk][0] * Sr[Xoff[chk][0]]
                                       + Cx[chk][1] * Sr[Xoff[chk][1]]
                                       + Cx[chk][2] * Sr[Xoff[chk][2]]
                                       + Cx[chk][3] * Sr[Xoff[chk][3]];
                        acc += Cy[chk][i] * rs;
                    }
                    op[bin] = acc;
                }
            }
            __syncthreads();
        }
    } else {
        // ---- fallback (unreachable for this distribution): direct gather ----
        const int c = tid;
        const float* fp = feat + (size_t)(b * 256 + c) * plane;
        float* op = out + ((size_t)r * 256 + c) * 49;

        for (int ph = 0; ph < 7; ph++) {
            #pragma unroll
            for (int pw = 0; pw < 7; pw++) {
                float acc = 0.0f;
                #pragma unroll
                for (int iy = 0; iy < 2; iy++) {
                    const int jy = 2 * ph + iy;
                    const float ly = s_ly[jy], hy = 1.0f - ly, vy = s_vy[jy];
                    const int ra = s_yl[jy] * W, rb = s_yh[jy] * W;
                    #pragma unroll
                    for (int ix = 0; ix < 2; ix++) {
                        const int jx = 2 * pw + ix;
                        const float lx = s_lx[jx], hx = 1.0f - lx, vx = s_vx[jx];
                        const int xl = s_xl[jx], xh = s_xh[jx];
                        const float bil = hy * (hx * fp[ra + xl] + lx * fp[ra + xh])
                                        + ly * (hx * fp[rb + xl] + lx * fp[rb + xh]);
                        acc += (vy * vx) * bil;
                    }
                }
                op[ph * 7 + pw] = acc * 0.25f;
            }
        }
    }
}

extern "C" void kernel_launch(void* const* d_in, const int* in_sizes, int n_in,
                              void* d_out, int out_size) {
    const int nroi = in_sizes[4] / 4;   // 512
    roi_align_kernel<<<nroi, 256>>>(
        (const float*)d_in[0], (const float*)d_in[1],
        (const float*)d_in[2], (const float*)d_in[3],
        (const float*)d_in[4], (float*)d_out);
}

// round 5
// speedup vs baseline: 3.4628x; 3.4628x over previous
#include <cuda_runtime.h>

// MultiScaleRoIAlign: 4-level FPN, RoIAlign(aligned=False), OUT=7, SR=2.
// feats: [2,256,200,200],[2,256,100,100],[2,256,50,50],[2,256,25,25] fp32
// boxes: [2,256,4] fp32 -> out: [512,256,7,7] fp32
//
// One block per RoI. Pipeline: cp.async-stage 4 channel regions into smem
// (double buffered) while computing the previous 4 channels' 49 bins each
// from smem via the separable bilinear form
//   acc = sum_i cy[i] * sum_j cx[j] * S[R[i] + X[j]]
// with per-bin geometry precomputed once into a smem table and hoisted to
// registers (constant across all 64 channel groups).

#define NLVL 4
#define GRP 4
#define NG 64            // 256 / GRP
#define MAXCELLS 1024

__device__ __forceinline__ unsigned smem_addr_u32(const void* p) {
    return (unsigned)__cvta_generic_to_shared(p);
}
__device__ __forceinline__ void cp_async4(unsigned dst, const float* src) {
    asm volatile("cp.async.ca.shared.global [%0], [%1], 4;\n" :: "r"(dst), "l"(src));
}
__device__ __forceinline__ void cp_commit() {
    asm volatile("cp.async.commit_group;\n" ::: "memory");
}
template <int N> __device__ __forceinline__ void cp_wait() {
    asm volatile("cp.async.wait_group %0;\n" :: "n"(N) : "memory");
}

__global__ __launch_bounds__(256) void roi_align_kernel(
    const float* __restrict__ f0, const float* __restrict__ f1,
    const float* __restrict__ f2, const float* __restrict__ f3,
    const float* __restrict__ boxes, float* __restrict__ out)
{
    const int r    = blockIdx.x;
    const int tid  = threadIdx.x;
    const int w    = tid >> 5;
    const int lane = tid & 31;
    const int b    = r >> 8;

    // ---- per-RoI geometry ----
    const float bx1 = boxes[r * 4 + 0];
    const float by1 = boxes[r * 4 + 1];
    const float bx2 = boxes[r * 4 + 2];
    const float by2 = boxes[r * 4 + 3];

    const float area = (bx2 - bx1) * (by2 - by1);
    float lv = floorf(4.0f + log2f(sqrtf(area) / 224.0f + 1e-6f));
    lv = fminf(fmaxf(lv, 2.0f), 5.0f);
    const int level = (int)lv - 2;

    const int   Htab[NLVL]  = {200, 100, 50, 25};
    const float sctab[NLVL] = {0.25f, 0.125f, 0.0625f, 0.03125f};
    const int   H  = Htab[level];
    const int   W  = H;
    const float sc = sctab[level];
    const float* feat = (level == 0) ? f0 : (level == 1) ? f1 : (level == 2) ? f2 : f3;

    const float x1 = bx1 * sc, y1 = by1 * sc;
    const float roi_w = fmaxf(bx2 * sc - x1, 1.0f);
    const float roi_h = fmaxf(by2 * sc - y1, 1.0f);
    const float bin_w = roi_w / 7.0f;
    const float bin_h = roi_h / 7.0f;

    // ---- sample tables ----
    __shared__ int   s_yl[14], s_yh[14], s_xl[14], s_xh[14];
    __shared__ float s_ly[14], s_lx[14], s_vy[14], s_vx[14];
    // per-bin geometry table (built once)
    __shared__ int   gR[4][49], gX[4][49];
    __shared__ float gCy[4][49], gCx[4][49];
    // double-buffered channel regions
    __shared__ float s_buf[2][GRP][MAXCELLS];   // 32 KB

    if (tid < 30) {
        const bool isx = (tid >= 16);
        const int  jj  = isx ? (tid - 16) : tid;
        if (jj < 14) {
            const int ph = jj >> 1;
            const int ii = jj & 1;
            const float g = (float)ph + ((float)ii + 0.5f) * 0.5f;
            float pos = isx ? (x1 + g * bin_w) : (y1 + g * bin_h);
            const float lim = (float)H;
            const float vld = (pos >= -1.0f && pos <= lim) ? 1.0f : 0.0f;
            pos = fmaxf(pos, 0.0f);
            int lo = (int)pos;
            int hi;
            if (lo >= H - 1) { lo = H - 1; hi = H - 1; pos = (float)lo; }
            else             { hi = lo + 1; }
            const float frac = pos - (float)lo;
            if (isx) { s_xl[jj] = lo; s_xh[jj] = hi; s_lx[jj] = frac; s_vx[jj] = vld; }
            else     { s_yl[jj] = lo; s_yh[jj] = hi; s_ly[jj] = frac; s_vy[jj] = vld; }
        }
    }
    __syncthreads();

    const int ry0 = s_yl[0], ry1 = s_yh[13];
    const int rx0 = s_xl[0], rx1 = s_xh[13];
    const int nrows = ry1 - ry0 + 1;
    const int ncols = rx1 - rx0 + 1;
    const int cells = nrows * ncols;

    const size_t plane = (size_t)H * W;

    if (cells <= MAXCELLS) {
        const float* fbase = feat + (size_t)b * 256 * plane + (size_t)ry0 * W + rx0;

        // staging lambda-ish: warp w stages channel (w&3) of group k,
        // rows starting (w>>2), stride 2.
        const int sch  = w & 3;
        const int srow = w >> 2;
        const unsigned buf0 = smem_addr_u32(&s_buf[0][sch][0]) + (unsigned)(srow * ncols) * 4u;
        const unsigned buf1 = smem_addr_u32(&s_buf[1][sch][0]) + (unsigned)(srow * ncols) * 4u;
        const int dstep = 2 * ncols * 4;

        // ---- prologue: stage group 0 ----
        {
            const float* fp = fbase + (size_t)sch * plane + (size_t)srow * W;
            unsigned dst = buf0;
            for (int row = srow; row < nrows; row += 2) {
                for (int col = lane; col < ncols; col += 32)
                    cp_async4(dst + (unsigned)col * 4u, fp + col);
                fp += 2 * W; dst += dstep;
            }
            cp_commit();
        }

        // ---- build per-bin geometry table ----
        if (tid < 49) {
            const int ph = tid / 7;
            const int pw = tid - ph * 7;
            #pragma unroll
            for (int s = 0; s < 2; s++) {
                const int jy = 2 * ph + s;
                const int jx = 2 * pw + s;
                const float vy = 0.25f * s_vy[jy];
                gR[2 * s + 0][tid] = (s_yl[jy] - ry0) * ncols;
                gR[2 * s + 1][tid] = (s_yh[jy] - ry0) * ncols;
                gCy[2 * s + 0][tid] = vy * (1.0f - s_ly[jy]);
                gCy[2 * s + 1][tid] = vy * s_ly[jy];
                gX[2 * s + 0][tid] = s_xl[jx] - rx0;
                gX[2 * s + 1][tid] = s_xh[jx] - rx0;
                gCx[2 * s + 0][tid] = s_vx[jx] * (1.0f - s_lx[jx]);
                gCx[2 * s + 1][tid] = s_vx[jx] * s_lx[jx];
            }
        }
        __syncthreads();

        // ---- hoist per-task geometry (task = (channel-in-group, bin)) ----
        const bool active = (tid < GRP * 49);
        int cg = 0, bin = 0;
        if (active) { cg = tid / 49; bin = tid - 49 * cg; }
        const int   r0 = gR[0][bin], r1 = gR[1][bin], r2 = gR[2][bin], r3 = gR[3][bin];
        const int   x0 = gX[0][bin], x1o = gX[1][bin], x2 = gX[2][bin], x3 = gX[3][bin];
        const float cy0 = gCy[0][bin], cy1 = gCy[1][bin], cy2 = gCy[2][bin], cy3 = gCy[3][bin];
        const float cx0 = gCx[0][bin], cx1 = gCx[1][bin], cx2 = gCx[2][bin], cx3 = gCx[3][bin];
        const float* S0 = &s_buf[0][cg][0];
        const float* S1 = &s_buf[1][cg][0];
        float* op = out + ((size_t)r * 256 + cg) * 49 + bin;

        // ---- pipelined group loop ----
        for (int g = 0; g < NG; g++) {
            // stage group g+1 into the other buffer
            if (g + 1 < NG) {
                const float* fp = fbase + (size_t)((g + 1) * GRP + sch) * plane + (size_t)srow * W;
                unsigned dst = ((g + 1) & 1) ? buf1 : buf0;
                for (int row = srow; row < nrows; row += 2) {
                    for (int col = lane; col < ncols; col += 32)
                        cp_async4(dst + (unsigned)col * 4u, fp + col);
                    fp += 2 * W; dst += dstep;
                }
            }
            cp_commit();
            cp_wait<1>();          // group g's data has landed
            __syncthreads();       // ... for ALL warps

            if (active) {
                const float* S = (g & 1) ? S1 : S0;
                const float* A = S + r0;
                const float* Bq = S + r1;
                const float* C = S + r2;
                const float* D = S + r3;
                float acc;
                acc  = cy0 * (cx0 * A[x0] + cx1 * A[x1o] + cx2 * A[x2] + cx3 * A[x3]);
                acc += cy1 * (cx0 * Bq[x0] + cx1 * Bq[x1o] + cx2 * Bq[x2] + cx3 * Bq[x3]);
                acc += cy2 * (cx0 * C[x0] + cx1 * C[x1o] + cx2 * C[x2] + cx3 * C[x3]);
                acc += cy3 * (cx0 * D[x0] + cx1 * D[x1o] + cx2 * D[x2] + cx3 * D[x3]);
                *op = acc;
                op += GRP * 49;
            }
            __syncthreads();       // compute(g) done before buf[g&1] is re-staged
        }
    } else {
        // ---- fallback (unreachable for this distribution): direct gather ----
        const int c = tid;
        const float* fp = feat + (size_t)(b * 256 + c) * plane;
        float* op = out + ((size_t)r * 256 + c) * 49;

        for (int ph = 0; ph < 7; ph++) {
            #pragma unroll
            for (int pw = 0; pw < 7; pw++) {
                float acc = 0.0f;
                #pragma unroll
                for (int iy = 0; iy < 2; iy++) {
                    const int jy = 2 * ph + iy;
                    const float ly = s_ly[jy], hy = 1.0f - ly, vy = s_vy[jy];
                    const int ra = s_yl[jy] * W, rb = s_yh[jy] * W;
                    #pragma unroll
                    for (int ix = 0; ix < 2; ix++) {
                        const int jx = 2 * pw + ix;
                        const float lx = s_lx[jx], hx = 1.0f - lx, vx = s_vx[jx];
                        const int xl = s_xl[jx], xh = s_xh[jx];
                        const float bil = hy * (hx * fp[ra + xl] + lx * fp[ra + xh])
                                        + ly * (hx * fp[rb + xl] + lx * fp[rb + xh]);
                        acc += (vy * vx) * bil;
                    }
                }
                op[ph * 7 + pw] = acc * 0.25f;
            }
        }
    }
}

extern "C" void kernel_launch(void* const* d_in, const int* in_sizes, int n_in,
                              void* d_out, int out_size) {
    const int nroi = in_sizes[4] / 4;   // 512
    roi_align_kernel<<<nroi, 256>>>(
        (const float*)d_in[0], (const float*)d_in[1],
        (const float*)d_in[2], (const float*)d_in[3],
        (const float*)d_in[4], (float*)d_out);
}